// round 16
// baseline (speedup 1.0000x reference)
#include <cuda_runtime.h>
#include <cuda_fp16.h>
#include <cstdint>

#define NROW 16384
#define NC   64
#define BM   128
#define BK   128
#define NIT  (NROW / BK)              /* 128 */

#define A_ROW_B 544                   /* 136 floats: 128 data + 8 pad */
#define X_ROW_B 272                   /* 68 floats:  64 data + 4 pad  */
#define A_STG_B (BM * A_ROW_B)        /* 69632 */
#define X_STG_B (BK * X_ROW_B)        /* 34816 */
#define STG_B   (A_STG_B + X_STG_B)   /* 104448 */
#define MAIN_SMEM (2 * STG_B)         /* 208896 dynamic (+9KB static wt) */

// ---------------------------------------------------------------------------
__device__ __forceinline__ uint32_t smem_u32(const void* p) {
    uint32_t a;
    asm("{ .reg .u64 t; cvta.to.shared.u64 t, %1; cvt.u32.u64 %0, t; }" : "=r"(a) : "l"(p));
    return a;
}
__device__ __forceinline__ void cp_async16(uint32_t saddr, const void* g) {
    asm volatile("cp.async.cg.shared.global [%0], [%1], 16;" :: "r"(saddr), "l"(g));
}
__device__ __forceinline__ uint32_t pack_h2(float lo, float hi) {
    uint32_t r;
    asm("cvt.rn.f16x2.f32 %0, %1, %2;" : "=r"(r) : "f"(hi), "f"(lo));
    return r;
}
__device__ __forceinline__ void mma_f16(float c[4], uint32_t a0, uint32_t a1,
                                        uint32_t a2, uint32_t a3,
                                        uint32_t b0, uint32_t b1) {
    asm volatile(
        "mma.sync.aligned.m16n8k16.row.col.f32.f16.f16.f32 "
        "{%0,%1,%2,%3},{%4,%5,%6,%7},{%8,%9},{%0,%1,%2,%3};"
        : "+f"(c[0]), "+f"(c[1]), "+f"(c[2]), "+f"(c[3])
        : "r"(a0), "r"(a1), "r"(a2), "r"(a3), "r"(b0), "r"(b1));
}

// ---------------------------------------------------------------------------
// Single kernel, no cross-CTA dependency:
//   agg = adj @ x   (mainloop, fp16 MMA, B-fragments packed from fp32 x tile)
//   out = agg @ w   (MMA epilogue: C-frags re-packed as A-frags, w^T fp16 smem)
// ---------------------------------------------------------------------------
__global__ void __launch_bounds__(128, 1) gcn_fused(const float* __restrict__ A,
                                                    const float* __restrict__ x,
                                                    const float* __restrict__ w,
                                                    float* __restrict__ out) {
    extern __shared__ char smem[];
    __shared__ __half wt[NC * 72];         // w^T fp16: wt[n*72 + c], 9 KB static
    const uint32_t smb = smem_u32(smem);

    const int t    = threadIdx.x;
    const int m0   = blockIdx.x * BM;
    const int warp = t >> 5, lane = t & 31;
    const int g    = lane >> 2;            // 0..7
    const int q    = lane & 3;             // 0..3

    // ---- per-thread cp.async plans ----
    // A: 32 chunks, chunk j -> row (j*4 + t>>5), seg (t&31); 262144B g / 2176B s
    const int ar = t >> 5, as = t & 31;
    const char* gA = (const char*)A + ((size_t)(m0 + ar) * NROW + (size_t)as * 4) * 4;
    const uint32_t sAo = (uint32_t)(ar * A_ROW_B + as * 16);
    // X: 16 chunks, chunk j -> k-row (j*8 + t>>4), seg (t&15); 2048B g / 2176B s
    const int xr = t >> 4, xs_ = t & 15;
    const char* gX = (const char*)x + ((size_t)xr * NC + (size_t)xs_ * 4) * 4;
    const uint32_t sXo = (uint32_t)(A_STG_B + xr * X_ROW_B + xs_ * 16);

    auto load_stage = [&](int st) {
        const uint32_t sb = smb + st * STG_B;
        #pragma unroll
        for (int j = 0; j < 32; ++j)
            cp_async16(sb + sAo + j * 2176u, gA + (size_t)j * 262144);
        #pragma unroll
        for (int j = 0; j < 16; ++j)
            cp_async16(sb + sXo + j * 2176u, gX + (size_t)j * 2048);
        gA += BK * 4;
        gX += (size_t)BK * NC * 4;
    };

    load_stage(0);
    asm volatile("cp.async.commit_group;");
    load_stage(1);
    asm volatile("cp.async.commit_group;");

    // ---- build w^T fp16 table (overlaps the A/X prefetch) ----
    #pragma unroll
    for (int i = 0; i < 32; ++i) {
        const int idx = i * 128 + t;           // w is [c][n] row-major
        const int c = idx >> 6, n = idx & 63;
        wt[n * 72 + c] = __float2half_rn(w[idx]);
    }
    __syncthreads();

    float acc[2][8][4];
    #pragma unroll
    for (int i = 0; i < 2; ++i)
        #pragma unroll
        for (int j = 0; j < 8; ++j)
            #pragma unroll
            for (int c = 0; c < 4; ++c) acc[i][j][c] = 0.f;

    for (int it = 0; it < NIT; ++it) {
        asm volatile("cp.async.wait_group 1;");
        __syncthreads();

        const int st = it & 1;
        const float* sA = (const float*)(smem + st * STG_B);
        const float* sX = (const float*)(smem + st * STG_B + A_STG_B);

        #pragma unroll
        for (int kt = 0; kt < 8; ++kt) {            // eight k16 tiles
            const int kb = kt * 16 + 2 * q;
            uint32_t b0[8], b1[8];
            #pragma unroll
            for (int j = 0; j < 8; ++j) {           // banks 8q+g(+c): bijective
                const int n = j * 8 + g;
                b0[j] = pack_h2(sX[(kb    ) * 68 + n], sX[(kb + 1) * 68 + n]);
                b1[j] = pack_h2(sX[(kb + 8) * 68 + n], sX[(kb + 9) * 68 + n]);
            }
            #pragma unroll
            for (int i = 0; i < 2; ++i) {
                const int R = warp * 32 + i * 16;
                float2 p0 = *(const float2*)&sA[(R + g)     * 136 + kb];
                float2 p1 = *(const float2*)&sA[(R + g + 8) * 136 + kb];
                float2 p2 = *(const float2*)&sA[(R + g)     * 136 + kb + 8];
                float2 p3 = *(const float2*)&sA[(R + g + 8) * 136 + kb + 8];
                uint32_t a0 = pack_h2(p0.x, p0.y);
                uint32_t a1 = pack_h2(p1.x, p1.y);
                uint32_t a2 = pack_h2(p2.x, p2.y);
                uint32_t a3 = pack_h2(p3.x, p3.y);
                #pragma unroll
                for (int j = 0; j < 8; ++j)
                    mma_f16(acc[i][j], a0, a1, a2, a3, b0[j], b1[j]);
            }
        }

        __syncthreads();
        if (it + 2 < NIT) load_stage(st);
        asm volatile("cp.async.commit_group;");     // keeps wait cadence
    }

    // ---- epilogue: out = agg @ w via MMA; C-frags re-pack as A-frags ----
    #pragma unroll
    for (int i = 0; i < 2; ++i) {
        float oa[8][4];
        #pragma unroll
        for (int j = 0; j < 8; ++j)
            #pragma unroll
            for (int c = 0; c < 4; ++c) oa[j][c] = 0.f;

        #pragma unroll
        for (int kt = 0; kt < 4; ++kt) {            // c-dim = 64 -> 4 k16 tiles
            // A-frag at k=16kt+2q: cols 8(2kt)+2q and 8(2kt+1)+2q of agg
            uint32_t a0 = pack_h2(acc[i][2 * kt    ][0], acc[i][2 * kt    ][1]);
            uint32_t a1 = pack_h2(acc[i][2 * kt    ][2], acc[i][2 * kt    ][3]);
            uint32_t a2 = pack_h2(acc[i][2 * kt + 1][0], acc[i][2 * kt + 1][1]);
            uint32_t a3 = pack_h2(acc[i][2 * kt + 1][2], acc[i][2 * kt + 1][3]);
            const int cb = kt * 16 + 2 * q;
            #pragma unroll
            for (int j = 0; j < 8; ++j) {           // banks 4g+q: bijective
                const int n = j * 8 + g;
                uint32_t b0 = *(const uint32_t*)&wt[n * 72 + cb];
                uint32_t b1 = *(const uint32_t*)&wt[n * 72 + cb + 8];
                mma_f16(oa[j], a0, a1, a2, a3, b0, b1);
            }
        }

        const int row = m0 + warp * 32 + i * 16 + g;
        #pragma unroll
        for (int j = 0; j < 8; ++j) {
            const int col = j * 8 + q * 2;
            *(float2*)(out + (size_t)row * NC + col)       = make_float2(oa[j][0], oa[j][1]);
            *(float2*)(out + (size_t)(row + 8) * NC + col) = make_float2(oa[j][2], oa[j][3]);
        }
    }
}

// ---------------------------------------------------------------------------
extern "C" void kernel_launch(void* const* d_in, const int* in_sizes, int n_in,
                              void* d_out, int out_size) {
    const float* x   = (const float*)d_in[0];   // [16384, 64]
    const float* adj = (const float*)d_in[1];   // [16384, 16384]
    const float* w   = (const float*)d_in[2];   // [64, 64]
    float* out = (float*)d_out;

    cudaFuncSetAttribute(gcn_fused, cudaFuncAttributeMaxDynamicSharedMemorySize, MAIN_SMEM);
    gcn_fused<<<NROW / BM, 128, MAIN_SMEM>>>(adj, x, w, out);
}

// round 17
// speedup vs baseline: 1.2271x; 1.2271x over previous
#include <cuda_runtime.h>
#include <cuda_fp16.h>
#include <cstdint>

#define NROW 16384
#define NC   64
#define BM   128
#define BK   128
#define NIT  (NROW / BK)              /* 128 */

#define A_ROW_B 544                   /* 136 floats: 128 data + 8 pad */
#define B_ROW_B 272                   /* 136 halves: 128 data + 8 pad */
#define A_STG_B (BM * A_ROW_B)        /* 69632 */
#define B_STG_B (NC * B_ROW_B)        /* 17408 */
#define STG_B   (A_STG_B + B_STG_B)   /* 87040 */
#define MAIN_SMEM (2 * STG_B)         /* 174080 */

__device__ __half g_Bh[(size_t)NC * NROW];   // (x@w)^T fp16, K-major, 2 MiB

// ---------------------------------------------------------------------------
__device__ __forceinline__ uint32_t smem_u32(const void* p) {
    uint32_t a;
    asm("{ .reg .u64 t; cvta.to.shared.u64 t, %1; cvt.u32.u64 %0, t; }" : "=r"(a) : "l"(p));
    return a;
}
__device__ __forceinline__ void cp_async16(uint32_t saddr, const void* g) {
    asm volatile("cp.async.cg.shared.global [%0], [%1], 16;" :: "r"(saddr), "l"(g));
}
__device__ __forceinline__ uint32_t pack_h2(float lo, float hi) {
    uint32_t r;
    asm("cvt.rn.f16x2.f32 %0, %1, %2;" : "=r"(r) : "f"(hi), "f"(lo));
    return r;
}
__device__ __forceinline__ void mma_f16(float c[4], uint32_t a0, uint32_t a1,
                                        uint32_t a2, uint32_t a3,
                                        uint32_t b0, uint32_t b1) {
    asm volatile(
        "mma.sync.aligned.m16n8k16.row.col.f32.f16.f16.f32 "
        "{%0,%1,%2,%3},{%4,%5,%6,%7},{%8,%9},{%0,%1,%2,%3};"
        : "+f"(c[0]), "+f"(c[1]), "+f"(c[2]), "+f"(c[3])
        : "r"(a0), "r"(a1), "r"(a2), "r"(a3), "r"(b0), "r"(b1));
}

// ---------------------------------------------------------------------------
// Kernel 1: g_Bh[n][k] = fp16( sum_c x[k][c] * w[c][n] )  (proven, unchanged)
// ---------------------------------------------------------------------------
__global__ void __launch_bounds__(128) xw_t(const float* __restrict__ x,
                                            const float* __restrict__ w) {
    __shared__ float  ws[NC * NC];
    __shared__ float  xs[32 * 65];
    __shared__ __half ts[NC * 48];
    const int t  = threadIdx.x;
    const int k0 = blockIdx.x * 32;

    #pragma unroll
    for (int j = 0; j < 8; ++j) ((float4*)ws)[j * 128 + t] = ((const float4*)w)[j * 128 + t];
    #pragma unroll
    for (int j = 0; j < 4; ++j) {
        int i4 = j * 128 + t;
        int r = i4 >> 4, c4 = i4 & 15;
        float4 v = ((const float4*)(x + (size_t)(k0 + r) * NC))[c4];
        float* d = xs + r * 65 + c4 * 4;
        d[0] = v.x; d[1] = v.y; d[2] = v.z; d[3] = v.w;
    }
    __syncthreads();

    const int r  = t & 31;
    const int n0 = (t >> 5) * 16;
    float acc[16];
    #pragma unroll
    for (int j = 0; j < 16; ++j) acc[j] = 0.f;
    #pragma unroll 8
    for (int c = 0; c < NC; ++c) {
        const float xv = xs[r * 65 + c];
        #pragma unroll
        for (int j4 = 0; j4 < 4; ++j4) {
            float4 wv = *(const float4*)&ws[c * NC + n0 + j4 * 4];
            acc[j4 * 4 + 0] += xv * wv.x;
            acc[j4 * 4 + 1] += xv * wv.y;
            acc[j4 * 4 + 2] += xv * wv.z;
            acc[j4 * 4 + 3] += xv * wv.w;
        }
    }
    #pragma unroll
    for (int j = 0; j < 16; ++j) ts[(n0 + j) * 48 + r] = __float2half_rn(acc[j]);
    __syncthreads();

    #pragma unroll
    for (int i = 0; i < 2; ++i) {
        const int i4 = i * 128 + t;
        const int n = i4 >> 2, c8 = i4 & 3;
        uint4 v = *(const uint4*)&ts[n * 48 + c8 * 8];
        *(uint4*)(g_Bh + (size_t)n * NROW + k0 + c8 * 8) = v;
    }
}

// ---------------------------------------------------------------------------
// Kernel 2 (PDL secondary): starts during xw_t, prefetches A (independent),
// then cudaGridDependencySynchronize() before any g_Bh-dependent load.
// Mainloop byte-identical to round 14.
// ---------------------------------------------------------------------------
__global__ void __launch_bounds__(128, 1) gcn_main(const float* __restrict__ A,
                                                   float* __restrict__ out) {
    extern __shared__ char smem[];
    const uint32_t smb = smem_u32(smem);

    const int t    = threadIdx.x;
    const int m0   = blockIdx.x * BM;
    const int warp = t >> 5, lane = t & 31;
    const int g    = lane >> 2;            // 0..7
    const int q    = lane & 3;             // 0..3

    float acc[2][8][4];
    #pragma unroll
    for (int i = 0; i < 2; ++i)
        #pragma unroll
        for (int j = 0; j < 8; ++j)
            #pragma unroll
            for (int c = 0; c < 4; ++c) acc[i][j][c] = 0.f;

    const int ar = t >> 5, as = t & 31;
    const int bn = t >> 4, bs = t & 15;
    const char* gA = (const char*)A + ((size_t)(m0 + ar) * NROW + (size_t)as * 4) * 4;
    const char* gB = (const char*)g_Bh + ((size_t)bn * NROW + (size_t)bs * 8) * 2;
    const uint32_t sAo = (uint32_t)(ar * A_ROW_B + as * 16);
    const uint32_t sBo = (uint32_t)(A_STG_B + bn * B_ROW_B + bs * 16);

    auto load_A = [&](int st) {
        const uint32_t sb = smb + st * STG_B;
        #pragma unroll
        for (int j = 0; j < 32; ++j)
            cp_async16(sb + sAo + j * 2176u, gA + (size_t)j * 262144);
        gA += BK * 4;
    };
    auto load_B = [&](int st) {
        const uint32_t sb = smb + st * STG_B;
        #pragma unroll
        for (int j = 0; j < 8; ++j)
            cp_async16(sb + sBo + j * 2176u, gB + (size_t)j * 262144);
        gB += BK * 2;
    };

    // A prefetch overlaps the tail of xw_t (adj is independent of it)
    load_A(0);
    asm volatile("cp.async.commit_group;");   // G0 = A0
    load_A(1);
    asm volatile("cp.async.commit_group;");   // G1 = A1

    // wait for xw_t completion (full memory visibility; no early trigger used)
    cudaGridDependencySynchronize();

    load_B(0);
    asm volatile("cp.async.commit_group;");   // G2 = B0
    load_B(1);
    asm volatile("cp.async.commit_group;");   // G3 = B1

    for (int it = 0; it < NIT; ++it) {
        // it=0: <=1 pending leaves G3 -> A0,A1,B0 complete (same as r14)
        asm volatile("cp.async.wait_group 1;");
        __syncthreads();

        const int st = it & 1;
        const float*  sA = (const float*)(smem + st * STG_B);
        const __half* sB = (const __half*)(smem + st * STG_B + A_STG_B);

        #pragma unroll
        for (int kt = 0; kt < 8; ++kt) {            // eight k16 tiles
            const int kb = kt * 16 + 2 * q;
            uint32_t b0[8], b1[8];
            #pragma unroll
            for (int j = 0; j < 8; ++j) {           // conflict-free
                const int n = j * 8 + g;
                b0[j] = *(const uint32_t*)&sB[n * 136 + kb];
                b1[j] = *(const uint32_t*)&sB[n * 136 + kb + 8];
            }
            #pragma unroll
            for (int i = 0; i < 2; ++i) {
                const int R = warp * 32 + i * 16;
                float2 p0 = *(const float2*)&sA[(R + g)     * 136 + kb];
                float2 p1 = *(const float2*)&sA[(R + g + 8) * 136 + kb];
                float2 p2 = *(const float2*)&sA[(R + g)     * 136 + kb + 8];
                float2 p3 = *(const float2*)&sA[(R + g + 8) * 136 + kb + 8];
                uint32_t a0 = pack_h2(p0.x, p0.y);
                uint32_t a1 = pack_h2(p1.x, p1.y);
                uint32_t a2 = pack_h2(p2.x, p2.y);
                uint32_t a3 = pack_h2(p3.x, p3.y);
                #pragma unroll
                for (int j = 0; j < 8; ++j)
                    mma_f16(acc[i][j], a0, a1, a2, a3, b0[j], b1[j]);
            }
        }

        __syncthreads();
        if (it + 2 < NIT) { load_A(st); load_B(st); }
        asm volatile("cp.async.commit_group;");     // keeps wait cadence
    }

    #pragma unroll
    for (int i = 0; i < 2; ++i) {
        #pragma unroll
        for (int j = 0; j < 8; ++j) {
            const int row = m0 + warp * 32 + i * 16 + g;
            const int col = j * 8 + q * 2;
            *(float2*)(out + (size_t)row * NC + col)       = make_float2(acc[i][j][0], acc[i][j][1]);
            *(float2*)(out + (size_t)(row + 8) * NC + col) = make_float2(acc[i][j][2], acc[i][j][3]);
        }
    }
}

// ---------------------------------------------------------------------------
extern "C" void kernel_launch(void* const* d_in, const int* in_sizes, int n_in,
                              void* d_out, int out_size) {
    const float* x   = (const float*)d_in[0];   // [16384, 64]
    const float* adj = (const float*)d_in[1];   // [16384, 16384]
    const float* w   = (const float*)d_in[2];   // [64, 64]
    float* out = (float*)d_out;

    cudaFuncSetAttribute(gcn_main, cudaFuncAttributeMaxDynamicSharedMemorySize, MAIN_SMEM);

    xw_t<<<NROW / 32, 128>>>(x, w);

    // PDL: gcn_main may start while xw_t is still running; it gates itself
    // with cudaGridDependencySynchronize() before touching g_Bh.
    cudaLaunchConfig_t cfg = {};
    cfg.gridDim        = dim3(NROW / BM, 1, 1);
    cfg.blockDim       = dim3(128, 1, 1);
    cfg.dynamicSmemBytes = MAIN_SMEM;
    cfg.stream         = 0;
    cudaLaunchAttribute attrs[1];
    attrs[0].id = cudaLaunchAttributeProgrammaticStreamSerialization;
    attrs[0].val.programmaticStreamSerializationAllowed = 1;
    cfg.attrs   = attrs;
    cfg.numAttrs = 1;
    cudaLaunchKernelEx(&cfg, gcn_main, adj, out);
}